// round 12
// baseline (speedup 1.0000x reference)
#include <cuda_runtime.h>
#include <cstdint>

#define NUM_G 1024
#define HID 256
#define OUTW 768
#define NWARP 6
#define NTHREAD 192
#define RPC 12                          // rows per chunk (12KB)
#define GRID 592                        // 148 SMs x 4 CTAs, all co-resident
#define PIECES_PER_G 4
#define NPIECE (NUM_G * PIECES_PER_G)   // 4096
#define NOUT (NUM_G * OUTW)
#define QD 8

__device__ int d_ticket;
__device__ int d_arrive;                // monotonic grid-barrier counter
__device__ int d_bounds[NUM_G + 1];

struct PieceQ { int start; int end; int g; float inv; };

__device__ __forceinline__ int load_gid(const void* b, int j, int is64) {
    return is64 ? ((const int*)b)[2 * j] : ((const int*)b)[j];
}

// Sign-aware float atomic max (correct vs -inf init and mixed signs).
__device__ __forceinline__ void atomicMaxFloat(float* addr, float v) {
    if (v >= 0.0f) atomicMax((int*)addr, __float_as_int(v));
    else           atomicMin((unsigned int*)addr, __float_as_uint(v));
}

__device__ __forceinline__ void mbar_init(uint32_t mbar, uint32_t count) {
    asm volatile("mbarrier.init.shared.b64 [%0], %1;" :: "r"(mbar), "r"(count) : "memory");
}
__device__ __forceinline__ void mbar_expect_tx(uint32_t mbar, uint32_t bytes) {
    asm volatile("mbarrier.arrive.expect_tx.shared.b64 _, [%0], %1;"
                 :: "r"(mbar), "r"(bytes) : "memory");
}
__device__ __forceinline__ void bulk_g2s(uint32_t sdst, const void* gsrc,
                                         uint32_t bytes, uint32_t mbar) {
    asm volatile("cp.async.bulk.shared::cta.global.mbarrier::complete_tx::bytes "
                 "[%0], [%1], %2, [%3];"
                 :: "r"(sdst), "l"(gsrc), "r"(bytes), "r"(mbar) : "memory");
}
__device__ __forceinline__ void mbar_wait(uint32_t mbar, uint32_t parity) {
    uint32_t done;
    asm volatile(
        "{\n\t.reg .pred p;\n\t"
        "mbarrier.try_wait.parity.acquire.cta.shared::cta.b64 p, [%1], %2;\n\t"
        "selp.b32 %0, 1, 0, p;\n\t}"
        : "=r"(done) : "r"(mbar), "r"(parity) : "memory");
    if (!done) {
        asm volatile(
            "{\n\t.reg .pred P1;\n\t"
            "WAIT_LOOP_%=:\n\t"
            "mbarrier.try_wait.parity.acquire.cta.shared::cta.b64 P1, [%0], %1, 0x989680;\n\t"
            "@P1 bra.uni WAIT_DONE_%=;\n\t"
            "bra.uni WAIT_LOOP_%=;\n\t"
            "WAIT_DONE_%=:\n\t}"
            :: "r"(mbar), "r"(parity) : "memory");
    }
}

__device__ __forceinline__ float dot8(const float4 a, const float4 b,
                                      const float4 wa, const float4 wb) {
    return a.x * wa.x + a.y * wa.y + a.z * wa.z + a.w * wa.w
         + b.x * wb.x + b.y * wb.y + b.z * wb.z + b.w * wb.w;
}

__device__ __forceinline__ void acc_node(const float4 a, const float4 b, float wt,
                                         float4& s0, float4& s1,
                                         float4& m0, float4& m1,
                                         float4& t0, float4& t1) {
    s0.x += a.x; s0.y += a.y; s0.z += a.z; s0.w += a.w;
    s1.x += b.x; s1.y += b.y; s1.z += b.z; s1.w += b.w;
    m0.x = fmaxf(m0.x, a.x); m0.y = fmaxf(m0.y, a.y);
    m0.z = fmaxf(m0.z, a.z); m0.w = fmaxf(m0.w, a.w);
    m1.x = fmaxf(m1.x, b.x); m1.y = fmaxf(m1.y, b.y);
    m1.z = fmaxf(m1.z, b.z); m1.w = fmaxf(m1.w, b.w);
    t0.x = fmaf(a.x, wt, t0.x); t0.y = fmaf(a.y, wt, t0.y);
    t0.z = fmaf(a.z, wt, t0.z); t0.w = fmaf(a.w, wt, t0.w);
    t1.x = fmaf(b.x, wt, t1.x); t1.y = fmaf(b.y, wt, t1.y);
    t1.z = fmaf(b.z, wt, t1.z); t1.w = fmaf(b.w, wt, t1.w);
}

__global__ __launch_bounds__(NTHREAD, 4)
void ensemble_pool_kernel(const float* __restrict__ x,
                          const void* __restrict__ batch_raw,
                          int n_nodes,
                          const float* __restrict__ att_w,
                          const float* __restrict__ att_b,
                          float* __restrict__ out) {
    __shared__ __align__(16) float4 sbuf[3][RPC][64];   // 36KB
    __shared__ __align__(8) unsigned long long mbar_store[3];
    __shared__ PieceQ q[QD];
    __shared__ int s_is64;

    const int warp = threadIdx.x >> 5;
    const int lane = threadIdx.x & 31;
    const int t = threadIdx.x;
    const int bid = blockIdx.x;

    const uint32_t mb0 = (uint32_t)__cvta_generic_to_shared(&mbar_store[0]);
    const uint32_t mb1 = (uint32_t)__cvta_generic_to_shared(&mbar_store[1]);
    const uint32_t mb2 = (uint32_t)__cvta_generic_to_shared(&mbar_store[2]);
    const uint32_t sd0 = (uint32_t)__cvta_generic_to_shared(&sbuf[0][0][0]);
    const uint32_t sd1 = (uint32_t)__cvta_generic_to_shared(&sbuf[1][0][0]);
    const uint32_t sd2 = (uint32_t)__cvta_generic_to_shared(&sbuf[2][0][0]);

    // ===== Phase 0: distributed setup (probe, bounds, out init, ticket reset) =====
    if (t == 0) {
        mbar_init(mb0, 1); mbar_init(mb1, 1); mbar_init(mb2, 1);
        const int* b32 = (const int*)batch_raw;
        int zeros = 0;
        int base = n_nodes / 2;
        for (int i = 0; i < 64; i++)
            if (b32[base + i] == 0) zeros++;
        s_is64 = (zeros > 16) ? 1 : 0;
        if (bid == 0) d_ticket = 0;   // happens-before barrier release
    }
    __syncthreads();
    const int is64 = s_is64;

    for (int i = bid * NTHREAD + t; i < n_nodes; i += GRID * NTHREAD) {
        const int cur = load_gid(batch_raw, i, is64);
        const int prev = (i == 0) ? -1 : load_gid(batch_raw, i - 1, is64);
        for (int g = prev + 1; g <= cur; g++) d_bounds[g] = i;
        if (i == n_nodes - 1)
            for (int g = cur + 1; g <= NUM_G; g++) d_bounds[g] = n_nodes;
    }
    for (int i = bid * NTHREAD + t; i < NOUT / 4; i += GRID * NTHREAD) {
        const int c = (i * 4) % OUTW;
        uint4 v = (c >= HID && c < 2 * HID)
                ? make_uint4(0xFF800000u, 0xFF800000u, 0xFF800000u, 0xFF800000u)  // -inf
                : make_uint4(0u, 0u, 0u, 0u);
        ((uint4*)out)[i] = v;
    }

    // ===== Grid barrier (monotonic counter; all 592 CTAs co-resident) =====
    __threadfence();     // release setup writes
    __syncthreads();     // whole CTA done with setup
    if (t == 0) {
        const int old = atomicAdd(&d_arrive, 1);
        const int target = (old / GRID + 1) * GRID;
        while (atomicAdd(&d_arrive, 0) < target) { }
        __threadfence();
    }
    __syncthreads();

    // ===== Phase 1: streaming pipeline =====
    const float4 w0 = reinterpret_cast<const float4*>(att_w)[lane];
    const float4 w1 = reinterpret_cast<const float4*>(att_w)[lane + 32];
    const float bias = att_b[0];
    const float NEG_INF = -__int_as_float(0x7f800000);
    const float* xf = x;

    // ---- producer state (thread 0 only) ----
    int pp_start = 0, pp_end = 0, pp_c = 0, pp_n = 0;
    int pf = 0;
    int prod_seq = 0;
    bool pdone = false;

    auto fetch_piece = [&]() -> bool {
        for (;;) {
            int p = atomicAdd(&d_ticket, 1);
            if (p >= NPIECE) {
                q[pf % QD].g = -1;
                pf++;
                pdone = true;
                return false;
            }
            const int g = p >> 2, e = p & 3;
            const int b = d_bounds[g];
            const int cnt = d_bounds[g + 1] - b;
            const int st = b + (cnt * e) / PIECES_PER_G;
            const int en = b + (cnt * (e + 1)) / PIECES_PER_G;
            PieceQ pq; pq.start = st; pq.end = en; pq.g = g;
            pq.inv = 1.0f / fmaxf((float)cnt, 1.0f);
            q[pf % QD] = pq; pf++;
            if (en > st) {
                pp_start = st; pp_end = en; pp_c = 0;
                pp_n = (en - st + RPC - 1) / RPC;
                return true;
            }
        }
    };

    auto issue_one = [&]() {
        if (pdone) return;
        if (pp_c == pp_n) { if (!fetch_piece()) return; }
        const int r0 = pp_start + pp_c * RPC;
        const int rows = min(RPC, pp_end - r0);
        const int st = prod_seq % 3;
        const uint32_t mb = (st == 0) ? mb0 : (st == 1) ? mb1 : mb2;
        const uint32_t sd = (st == 0) ? sd0 : (st == 1) ? sd1 : sd2;
        const uint32_t bytes = (uint32_t)rows * HID * 4;
        mbar_expect_tx(mb, bytes);
        bulk_g2s(sd, xf + (size_t)r0 * HID, bytes, mb);
        prod_seq++; pp_c++;
    };

    if (t == 0) { issue_one(); issue_one(); }   // prime 2 ahead
    __syncthreads();

    // ---- consumer ----
    int cons_seq = 0;
    int cons_pidx = 0;

    for (;;) {
        const PieceQ pc = q[cons_pidx % QD];
        cons_pidx++;
        if (pc.g < 0) break;
        const int total = pc.end - pc.start;
        if (total <= 0) continue;
        const int nch = (total + RPC - 1) / RPC;

        float4 sum0 = make_float4(0.f, 0.f, 0.f, 0.f);
        float4 sum1 = make_float4(0.f, 0.f, 0.f, 0.f);
        float4 att0 = make_float4(0.f, 0.f, 0.f, 0.f);
        float4 att1 = make_float4(0.f, 0.f, 0.f, 0.f);
        float4 mx0  = make_float4(NEG_INF, NEG_INF, NEG_INF, NEG_INF);
        float4 mx1  = make_float4(NEG_INF, NEG_INF, NEG_INF, NEG_INF);

        for (int c = 0; c < nch; c++) {
            if (t == 0) issue_one();   // continuous stream, crosses pieces

            const int st = cons_seq % 3;
            const uint32_t mbw = (st == 0) ? mb0 : (st == 1) ? mb1 : mb2;
            mbar_wait(mbw, (cons_seq / 3) & 1);

            const int r0 = pc.start + c * RPC;
            const int rows = min(RPC, pc.end - r0);
            const int wr = 2 * warp;

            if (wr + 1 < rows) {
                const float4 a0 = sbuf[st][wr][lane];
                const float4 b0 = sbuf[st][wr][lane + 32];
                const float4 a1 = sbuf[st][wr + 1][lane];
                const float4 b1 = sbuf[st][wr + 1][lane + 32];

                float p0 = dot8(a0, b0, w0, w1);
                float p1 = dot8(a1, b1, w0, w1);
                #pragma unroll
                for (int off = 16; off > 0; off >>= 1) {
                    p0 += __shfl_xor_sync(0xffffffffu, p0, off);
                    p1 += __shfl_xor_sync(0xffffffffu, p1, off);
                }
                const float wt0 = 1.0f / (1.0f + __expf(-(p0 + bias)));
                const float wt1 = 1.0f / (1.0f + __expf(-(p1 + bias)));
                acc_node(a0, b0, wt0, sum0, sum1, mx0, mx1, att0, att1);
                acc_node(a1, b1, wt1, sum0, sum1, mx0, mx1, att0, att1);
            } else if (wr < rows) {
                const float4 a0 = sbuf[st][wr][lane];
                const float4 b0 = sbuf[st][wr][lane + 32];
                float p0 = dot8(a0, b0, w0, w1);
                #pragma unroll
                for (int off = 16; off > 0; off >>= 1)
                    p0 += __shfl_xor_sync(0xffffffffu, p0, off);
                const float wt0 = 1.0f / (1.0f + __expf(-(p0 + bias)));
                acc_node(a0, b0, wt0, sum0, sum1, mx0, mx1, att0, att1);
            }

            __syncthreads();   // stage consumed before reuse 3 seqs later
            cons_seq++;
        }

        // ===== Fire-and-forget epilogue: per-warp direct atomics, no barriers =====
        float* orow = out + (size_t)pc.g * OUTW;
        const int c0 = 4 * lane;
        const int c1 = 128 + 4 * lane;
        const float inv = pc.inv;

        // MEAN (scaled partial; division distributes over piece sums)
        atomicAdd(&orow[c0 + 0], sum0.x * inv);
        atomicAdd(&orow[c0 + 1], sum0.y * inv);
        atomicAdd(&orow[c0 + 2], sum0.z * inv);
        atomicAdd(&orow[c0 + 3], sum0.w * inv);
        atomicAdd(&orow[c1 + 0], sum1.x * inv);
        atomicAdd(&orow[c1 + 1], sum1.y * inv);
        atomicAdd(&orow[c1 + 2], sum1.z * inv);
        atomicAdd(&orow[c1 + 3], sum1.w * inv);
        // MAX
        atomicMaxFloat(&orow[HID + c0 + 0], mx0.x);
        atomicMaxFloat(&orow[HID + c0 + 1], mx0.y);
        atomicMaxFloat(&orow[HID + c0 + 2], mx0.z);
        atomicMaxFloat(&orow[HID + c0 + 3], mx0.w);
        atomicMaxFloat(&orow[HID + c1 + 0], mx1.x);
        atomicMaxFloat(&orow[HID + c1 + 1], mx1.y);
        atomicMaxFloat(&orow[HID + c1 + 2], mx1.z);
        atomicMaxFloat(&orow[HID + c1 + 3], mx1.w);
        // ATT
        atomicAdd(&orow[2 * HID + c0 + 0], att0.x);
        atomicAdd(&orow[2 * HID + c0 + 1], att0.y);
        atomicAdd(&orow[2 * HID + c0 + 2], att0.z);
        atomicAdd(&orow[2 * HID + c0 + 3], att0.w);
        atomicAdd(&orow[2 * HID + c1 + 0], att1.x);
        atomicAdd(&orow[2 * HID + c1 + 1], att1.y);
        atomicAdd(&orow[2 * HID + c1 + 2], att1.z);
        atomicAdd(&orow[2 * HID + c1 + 3], att1.w);
    }
}

extern "C" void kernel_launch(void* const* d_in, const int* in_sizes, int n_in,
                              void* d_out, int out_size) {
    const float* x     = (const float*)d_in[0];
    const void*  batch = d_in[1];
    const float* att_w = (const float*)d_in[2];
    const float* att_b = (const float*)d_in[3];
    float*       out   = (float*)d_out;
    const int n_nodes = in_sizes[1];

    ensemble_pool_kernel<<<GRID, NTHREAD>>>(x, batch, n_nodes, att_w, att_b, out);
}

// round 13
// speedup vs baseline: 1.5622x; 1.5622x over previous
#include <cuda_runtime.h>
#include <cstdint>

#define NUM_G 1024
#define HID 256
#define OUTW 768
#define NWARP 6
#define NTHREAD 192
#define RPC 12                          // rows per chunk (12KB)
#define GRID 592                        // 148 SMs x 4 CTAs, all co-resident
#define PIECES_PER_G 4
#define NPIECE (NUM_G * PIECES_PER_G)   // 4096
#define NOUT (NUM_G * OUTW)
#define QD 8

__device__ int d_ticket;
__device__ int d_arrive;                // monotonic grid-barrier counter
__device__ int d_bounds[NUM_G + 1];

struct PieceQ { int start; int end; int g; float inv; };

__device__ __forceinline__ int load_gid(const void* b, int j, int is64) {
    return is64 ? ((const int*)b)[2 * j] : ((const int*)b)[j];
}

// Sign-aware float atomic max (correct vs -inf init and mixed signs).
__device__ __forceinline__ void atomicMaxFloat(float* addr, float v) {
    if (v >= 0.0f) atomicMax((int*)addr, __float_as_int(v));
    else           atomicMin((unsigned int*)addr, __float_as_uint(v));
}

__device__ __forceinline__ void mbar_init(uint32_t mbar, uint32_t count) {
    asm volatile("mbarrier.init.shared.b64 [%0], %1;" :: "r"(mbar), "r"(count) : "memory");
}
__device__ __forceinline__ void mbar_expect_tx(uint32_t mbar, uint32_t bytes) {
    asm volatile("mbarrier.arrive.expect_tx.shared.b64 _, [%0], %1;"
                 :: "r"(mbar), "r"(bytes) : "memory");
}
__device__ __forceinline__ void bulk_g2s(uint32_t sdst, const void* gsrc,
                                         uint32_t bytes, uint32_t mbar) {
    asm volatile("cp.async.bulk.shared::cta.global.mbarrier::complete_tx::bytes "
                 "[%0], [%1], %2, [%3];"
                 :: "r"(sdst), "l"(gsrc), "r"(bytes), "r"(mbar) : "memory");
}
__device__ __forceinline__ void mbar_wait(uint32_t mbar, uint32_t parity) {
    uint32_t done;
    asm volatile(
        "{\n\t.reg .pred p;\n\t"
        "mbarrier.try_wait.parity.acquire.cta.shared::cta.b64 p, [%1], %2;\n\t"
        "selp.b32 %0, 1, 0, p;\n\t}"
        : "=r"(done) : "r"(mbar), "r"(parity) : "memory");
    if (!done) {
        asm volatile(
            "{\n\t.reg .pred P1;\n\t"
            "WAIT_LOOP_%=:\n\t"
            "mbarrier.try_wait.parity.acquire.cta.shared::cta.b64 P1, [%0], %1, 0x989680;\n\t"
            "@P1 bra.uni WAIT_DONE_%=;\n\t"
            "bra.uni WAIT_LOOP_%=;\n\t"
            "WAIT_DONE_%=:\n\t}"
            :: "r"(mbar), "r"(parity) : "memory");
    }
}

__device__ __forceinline__ float dot8(const float4 a, const float4 b,
                                      const float4 wa, const float4 wb) {
    return a.x * wa.x + a.y * wa.y + a.z * wa.z + a.w * wa.w
         + b.x * wb.x + b.y * wb.y + b.z * wb.z + b.w * wb.w;
}

__device__ __forceinline__ void acc_node(const float4 a, const float4 b, float wt,
                                         float4& s0, float4& s1,
                                         float4& m0, float4& m1,
                                         float4& t0, float4& t1) {
    s0.x += a.x; s0.y += a.y; s0.z += a.z; s0.w += a.w;
    s1.x += b.x; s1.y += b.y; s1.z += b.z; s1.w += b.w;
    m0.x = fmaxf(m0.x, a.x); m0.y = fmaxf(m0.y, a.y);
    m0.z = fmaxf(m0.z, a.z); m0.w = fmaxf(m0.w, a.w);
    m1.x = fmaxf(m1.x, b.x); m1.y = fmaxf(m1.y, b.y);
    m1.z = fmaxf(m1.z, b.z); m1.w = fmaxf(m1.w, b.w);
    t0.x = fmaf(a.x, wt, t0.x); t0.y = fmaf(a.y, wt, t0.y);
    t0.z = fmaf(a.z, wt, t0.z); t0.w = fmaf(a.w, wt, t0.w);
    t1.x = fmaf(b.x, wt, t1.x); t1.y = fmaf(b.y, wt, t1.y);
    t1.z = fmaf(b.z, wt, t1.z); t1.w = fmaf(b.w, wt, t1.w);
}

__global__ __launch_bounds__(NTHREAD, 4)
void ensemble_pool_kernel(const float* __restrict__ x,
                          const void* __restrict__ batch_raw,
                          int n_nodes,
                          const float* __restrict__ att_w,
                          const float* __restrict__ att_b,
                          float* __restrict__ out) {
    __shared__ __align__(16) float4 sbuf[3][RPC][64];   // 36KB
    __shared__ float s_part[NWARP][HID];                // 6KB
    __shared__ __align__(8) unsigned long long mbar_store[3];
    __shared__ PieceQ q[QD];
    __shared__ int s_is64;

    const int warp = threadIdx.x >> 5;
    const int lane = threadIdx.x & 31;
    const int t = threadIdx.x;
    const int bid = blockIdx.x;

    const uint32_t mb0 = (uint32_t)__cvta_generic_to_shared(&mbar_store[0]);
    const uint32_t mb1 = (uint32_t)__cvta_generic_to_shared(&mbar_store[1]);
    const uint32_t mb2 = (uint32_t)__cvta_generic_to_shared(&mbar_store[2]);
    const uint32_t sd0 = (uint32_t)__cvta_generic_to_shared(&sbuf[0][0][0]);
    const uint32_t sd1 = (uint32_t)__cvta_generic_to_shared(&sbuf[1][0][0]);
    const uint32_t sd2 = (uint32_t)__cvta_generic_to_shared(&sbuf[2][0][0]);

    // ===== Phase 0: distributed setup (probe, bounds, out init, ticket reset) =====
    if (t == 0) {
        mbar_init(mb0, 1); mbar_init(mb1, 1); mbar_init(mb2, 1);
        const int* b32 = (const int*)batch_raw;
        int zeros = 0;
        int base = n_nodes / 2;
        for (int i = 0; i < 64; i++)
            if (b32[base + i] == 0) zeros++;
        s_is64 = (zeros > 16) ? 1 : 0;
        if (bid == 0) d_ticket = 0;   // released by the barrier below
    }
    __syncthreads();
    const int is64 = s_is64;

    for (int i = bid * NTHREAD + t; i < n_nodes; i += GRID * NTHREAD) {
        const int cur = load_gid(batch_raw, i, is64);
        const int prev = (i == 0) ? -1 : load_gid(batch_raw, i - 1, is64);
        for (int g = prev + 1; g <= cur; g++) d_bounds[g] = i;
        if (i == n_nodes - 1)
            for (int g = cur + 1; g <= NUM_G; g++) d_bounds[g] = n_nodes;
    }
    for (int i = bid * NTHREAD + t; i < NOUT / 4; i += GRID * NTHREAD) {
        const int c = (i * 4) % OUTW;
        uint4 v = (c >= HID && c < 2 * HID)
                ? make_uint4(0xFF800000u, 0xFF800000u, 0xFF800000u, 0xFF800000u)  // -inf
                : make_uint4(0u, 0u, 0u, 0u);
        ((uint4*)out)[i] = v;
    }

    // ===== Grid barrier: arrive via atomic once, poll via plain LD (no RMW) =====
    __threadfence();     // release setup writes
    __syncthreads();
    if (t == 0) {
        const int old = atomicAdd(&d_arrive, 1);
        const int target = (old / GRID + 1) * GRID;
        volatile int* va = &d_arrive;
        while (*va < target) __nanosleep(64);
        __threadfence();  // acquire: setup writes of all CTAs visible
    }
    __syncthreads();

    // ===== Phase 1: streaming pipeline (identical to the 87.9us version) =====
    const float4 w0 = reinterpret_cast<const float4*>(att_w)[lane];
    const float4 w1 = reinterpret_cast<const float4*>(att_w)[lane + 32];
    const float bias = att_b[0];
    const float NEG_INF = -__int_as_float(0x7f800000);
    const float* xf = x;

    // ---- producer state (thread 0 only) ----
    int pp_start = 0, pp_end = 0, pp_c = 0, pp_n = 0;
    int pf = 0;
    int prod_seq = 0;
    bool pdone = false;

    auto fetch_piece = [&]() -> bool {
        for (;;) {
            int p = atomicAdd(&d_ticket, 1);
            if (p >= NPIECE) {
                q[pf % QD].g = -1;
                pf++;
                pdone = true;
                return false;
            }
            const int g = p >> 2, e = p & 3;
            const int b = d_bounds[g];
            const int cnt = d_bounds[g + 1] - b;
            const int st = b + (cnt * e) / PIECES_PER_G;
            const int en = b + (cnt * (e + 1)) / PIECES_PER_G;
            PieceQ pq; pq.start = st; pq.end = en; pq.g = g;
            pq.inv = 1.0f / fmaxf((float)cnt, 1.0f);
            q[pf % QD] = pq; pf++;
            if (en > st) {
                pp_start = st; pp_end = en; pp_c = 0;
                pp_n = (en - st + RPC - 1) / RPC;
                return true;
            }
        }
    };

    auto issue_one = [&]() {
        if (pdone) return;
        if (pp_c == pp_n) { if (!fetch_piece()) return; }
        const int r0 = pp_start + pp_c * RPC;
        const int rows = min(RPC, pp_end - r0);
        const int st = prod_seq % 3;
        const uint32_t mb = (st == 0) ? mb0 : (st == 1) ? mb1 : mb2;
        const uint32_t sd = (st == 0) ? sd0 : (st == 1) ? sd1 : sd2;
        const uint32_t bytes = (uint32_t)rows * HID * 4;
        mbar_expect_tx(mb, bytes);
        bulk_g2s(sd, xf + (size_t)r0 * HID, bytes, mb);
        prod_seq++; pp_c++;
    };

    if (t == 0) { issue_one(); issue_one(); }   // prime 2 ahead
    __syncthreads();

    // ---- consumer ----
    int cons_seq = 0;
    int cons_pidx = 0;

    for (;;) {
        const PieceQ pc = q[cons_pidx % QD];
        cons_pidx++;
        if (pc.g < 0) break;
        const int total = pc.end - pc.start;
        if (total <= 0) continue;
        const int nch = (total + RPC - 1) / RPC;

        float4 sum0 = make_float4(0.f, 0.f, 0.f, 0.f);
        float4 sum1 = make_float4(0.f, 0.f, 0.f, 0.f);
        float4 att0 = make_float4(0.f, 0.f, 0.f, 0.f);
        float4 att1 = make_float4(0.f, 0.f, 0.f, 0.f);
        float4 mx0  = make_float4(NEG_INF, NEG_INF, NEG_INF, NEG_INF);
        float4 mx1  = make_float4(NEG_INF, NEG_INF, NEG_INF, NEG_INF);

        for (int c = 0; c < nch; c++) {
            if (t == 0) issue_one();   // continuous stream, crosses pieces

            const int st = cons_seq % 3;
            const uint32_t mbw = (st == 0) ? mb0 : (st == 1) ? mb1 : mb2;
            mbar_wait(mbw, (cons_seq / 3) & 1);

            const int r0 = pc.start + c * RPC;
            const int rows = min(RPC, pc.end - r0);
            const int wr = 2 * warp;

            if (wr + 1 < rows) {
                const float4 a0 = sbuf[st][wr][lane];
                const float4 b0 = sbuf[st][wr][lane + 32];
                const float4 a1 = sbuf[st][wr + 1][lane];
                const float4 b1 = sbuf[st][wr + 1][lane + 32];

                float p0 = dot8(a0, b0, w0, w1);
                float p1 = dot8(a1, b1, w0, w1);
                #pragma unroll
                for (int off = 16; off > 0; off >>= 1) {
                    p0 += __shfl_xor_sync(0xffffffffu, p0, off);
                    p1 += __shfl_xor_sync(0xffffffffu, p1, off);
                }
                const float wt0 = 1.0f / (1.0f + __expf(-(p0 + bias)));
                const float wt1 = 1.0f / (1.0f + __expf(-(p1 + bias)));
                acc_node(a0, b0, wt0, sum0, sum1, mx0, mx1, att0, att1);
                acc_node(a1, b1, wt1, sum0, sum1, mx0, mx1, att0, att1);
            } else if (wr < rows) {
                const float4 a0 = sbuf[st][wr][lane];
                const float4 b0 = sbuf[st][wr][lane + 32];
                float p0 = dot8(a0, b0, w0, w1);
                #pragma unroll
                for (int off = 16; off > 0; off >>= 1)
                    p0 += __shfl_xor_sync(0xffffffffu, p0, off);
                const float wt0 = 1.0f / (1.0f + __expf(-(p0 + bias)));
                acc_node(a0, b0, wt0, sum0, sum1, mx0, mx1, att0, att1);
            }

            __syncthreads();   // stage consumed before reuse 3 seqs later
            cons_seq++;
        }

        // ===== Epilogue: CTA-combined partials, then one atomic per column =====
        float* orow = out + (size_t)pc.g * OUTW;

        // --- MEAN (scaled partial; division distributes over piece sums) ---
        reinterpret_cast<float4*>(&s_part[warp][4 * lane])[0]       = sum0;
        reinterpret_cast<float4*>(&s_part[warp][128 + 4 * lane])[0] = sum1;
        __syncthreads();
        {
            float acc = 0.f;
            #pragma unroll
            for (int w = 0; w < NWARP; w++) acc += s_part[w][t];
            atomicAdd(&orow[t], acc * pc.inv);
            if (t < HID - NTHREAD) {
                const int c = NTHREAD + t;
                float acc2 = 0.f;
                #pragma unroll
                for (int w = 0; w < NWARP; w++) acc2 += s_part[w][c];
                atomicAdd(&orow[c], acc2 * pc.inv);
            }
        }
        __syncthreads();

        // --- MAX ---
        reinterpret_cast<float4*>(&s_part[warp][4 * lane])[0]       = mx0;
        reinterpret_cast<float4*>(&s_part[warp][128 + 4 * lane])[0] = mx1;
        __syncthreads();
        {
            float acc = NEG_INF;
            #pragma unroll
            for (int w = 0; w < NWARP; w++) acc = fmaxf(acc, s_part[w][t]);
            atomicMaxFloat(&orow[HID + t], acc);
            if (t < HID - NTHREAD) {
                const int c = NTHREAD + t;
                float acc2 = NEG_INF;
                #pragma unroll
                for (int w = 0; w < NWARP; w++) acc2 = fmaxf(acc2, s_part[w][c]);
                atomicMaxFloat(&orow[HID + c], acc2);
            }
        }
        __syncthreads();

        // --- ATT ---
        reinterpret_cast<float4*>(&s_part[warp][4 * lane])[0]       = att0;
        reinterpret_cast<float4*>(&s_part[warp][128 + 4 * lane])[0] = att1;
        __syncthreads();
        {
            float acc = 0.f;
            #pragma unroll
            for (int w = 0; w < NWARP; w++) acc += s_part[w][t];
            atomicAdd(&orow[2 * HID + t], acc);
            if (t < HID - NTHREAD) {
                const int c = NTHREAD + t;
                float acc2 = 0.f;
                #pragma unroll
                for (int w = 0; w < NWARP; w++) acc2 += s_part[w][c];
                atomicAdd(&orow[2 * HID + c], acc2);
            }
        }
        __syncthreads();
    }
}

extern "C" void kernel_launch(void* const* d_in, const int* in_sizes, int n_in,
                              void* d_out, int out_size) {
    const float* x     = (const float*)d_in[0];
    const void*  batch = d_in[1];
    const float* att_w = (const float*)d_in[2];
    const float* att_b = (const float*)d_in[3];
    float*       out   = (float*)d_out;
    const int n_nodes = in_sizes[1];

    ensemble_pool_kernel<<<GRID, NTHREAD>>>(x, batch, n_nodes, att_w, att_b, out);
}

// round 14
// speedup vs baseline: 1.6017x; 1.0253x over previous
#include <cuda_runtime.h>
#include <cstdint>

#define NUM_G 1024
#define HID 256
#define OUTW 768
#define NWARP 6
#define NTHREAD 192
#define RPC 12                          // rows per chunk (12KB)
#define NSTAGE 4
#define GRID 592                        // 148 SMs x 4 CTAs
#define PIECES_PER_G 4
#define NPIECE (NUM_G * PIECES_PER_G)   // 4096
#define NOUT (NUM_G * OUTW)
#define QD 8
#define SBUF_BYTES (NSTAGE * RPC * HID * 4)   // 49152

__device__ int d_ticket;
__device__ int d_bounds[NUM_G + 1];

struct PieceQ { int start; int end; int g; float inv; };

__device__ __forceinline__ int load_gid(const void* b, int j, int is64) {
    return is64 ? ((const int*)b)[2 * j] : ((const int*)b)[j];
}

// Fused setup: dtype probe, segment bounds, vectorized out init, ticket reset.
__global__ void setup_kernel(const void* __restrict__ batch_raw, int n_nodes,
                             float* __restrict__ out) {
    __shared__ int s_is64;
    if (threadIdx.x == 0) {
        const int* b32 = (const int*)batch_raw;
        int zeros = 0;
        int base = n_nodes / 2;
        for (int i = 0; i < 64; i++)
            if (b32[base + i] == 0) zeros++;
        s_is64 = (zeros > 16) ? 1 : 0;
    }
    __syncthreads();
    const int is64 = s_is64;

    const int i = blockIdx.x * blockDim.x + threadIdx.x;
    if (i == 0) d_ticket = 0;

    if (i < n_nodes) {
        const int cur = load_gid(batch_raw, i, is64);
        const int prev = (i == 0) ? -1 : load_gid(batch_raw, i - 1, is64);
        for (int g = prev + 1; g <= cur; g++) d_bounds[g] = i;
        if (i == n_nodes - 1)
            for (int g = cur + 1; g <= NUM_G; g++) d_bounds[g] = n_nodes;
    }

    if (i < NOUT / 4) {
        const int c = (i * 4) % OUTW;
        uint4 v = (c >= HID && c < 2 * HID)
                ? make_uint4(0xFF800000u, 0xFF800000u, 0xFF800000u, 0xFF800000u)  // -inf
                : make_uint4(0u, 0u, 0u, 0u);
        ((uint4*)out)[i] = v;
    }
}

// Sign-aware float atomic max.
__device__ __forceinline__ void atomicMaxFloat(float* addr, float v) {
    if (v >= 0.0f) atomicMax((int*)addr, __float_as_int(v));
    else           atomicMin((unsigned int*)addr, __float_as_uint(v));
}

__device__ __forceinline__ void mbar_init(uint32_t mbar, uint32_t count) {
    asm volatile("mbarrier.init.shared.b64 [%0], %1;" :: "r"(mbar), "r"(count) : "memory");
}
__device__ __forceinline__ void mbar_expect_tx(uint32_t mbar, uint32_t bytes) {
    asm volatile("mbarrier.arrive.expect_tx.shared.b64 _, [%0], %1;"
                 :: "r"(mbar), "r"(bytes) : "memory");
}
__device__ __forceinline__ void bulk_g2s(uint32_t sdst, const void* gsrc,
                                         uint32_t bytes, uint32_t mbar) {
    asm volatile("cp.async.bulk.shared::cta.global.mbarrier::complete_tx::bytes "
                 "[%0], [%1], %2, [%3];"
                 :: "r"(sdst), "l"(gsrc), "r"(bytes), "r"(mbar) : "memory");
}
__device__ __forceinline__ void mbar_wait(uint32_t mbar, uint32_t parity) {
    uint32_t done;
    asm volatile(
        "{\n\t.reg .pred p;\n\t"
        "mbarrier.try_wait.parity.acquire.cta.shared::cta.b64 p, [%1], %2;\n\t"
        "selp.b32 %0, 1, 0, p;\n\t}"
        : "=r"(done) : "r"(mbar), "r"(parity) : "memory");
    if (!done) {
        asm volatile(
            "{\n\t.reg .pred P1;\n\t"
            "WAIT_LOOP_%=:\n\t"
            "mbarrier.try_wait.parity.acquire.cta.shared::cta.b64 P1, [%0], %1, 0x989680;\n\t"
            "@P1 bra.uni WAIT_DONE_%=;\n\t"
            "bra.uni WAIT_LOOP_%=;\n\t"
            "WAIT_DONE_%=:\n\t}"
            :: "r"(mbar), "r"(parity) : "memory");
    }
}

__device__ __forceinline__ float dot8(const float4 a, const float4 b,
                                      const float4 wa, const float4 wb) {
    return a.x * wa.x + a.y * wa.y + a.z * wa.z + a.w * wa.w
         + b.x * wb.x + b.y * wb.y + b.z * wb.z + b.w * wb.w;
}

__device__ __forceinline__ void acc_node(const float4 a, const float4 b, float wt,
                                         float4& s0, float4& s1,
                                         float4& m0, float4& m1,
                                         float4& t0, float4& t1) {
    s0.x += a.x; s0.y += a.y; s0.z += a.z; s0.w += a.w;
    s1.x += b.x; s1.y += b.y; s1.z += b.z; s1.w += b.w;
    m0.x = fmaxf(m0.x, a.x); m0.y = fmaxf(m0.y, a.y);
    m0.z = fmaxf(m0.z, a.z); m0.w = fmaxf(m0.w, a.w);
    m1.x = fmaxf(m1.x, b.x); m1.y = fmaxf(m1.y, b.y);
    m1.z = fmaxf(m1.z, b.z); m1.w = fmaxf(m1.w, b.w);
    t0.x = fmaf(a.x, wt, t0.x); t0.y = fmaf(a.y, wt, t0.y);
    t0.z = fmaf(a.z, wt, t0.z); t0.w = fmaf(a.w, wt, t0.w);
    t1.x = fmaf(b.x, wt, t1.x); t1.y = fmaf(b.y, wt, t1.y);
    t1.z = fmaf(b.z, wt, t1.z); t1.w = fmaf(b.w, wt, t1.w);
}

__global__ __launch_bounds__(NTHREAD, 4)
void ensemble_pool_kernel(const float* __restrict__ x,
                          const float* __restrict__ att_w,
                          const float* __restrict__ att_b,
                          float* __restrict__ out) {
    extern __shared__ __align__(16) float4 sbuf[];      // NSTAGE x RPC x 64 (48KB dynamic)
    __shared__ float s_part[NWARP][HID];                // 6KB static
    __shared__ __align__(8) unsigned long long mbar_store[NSTAGE];
    __shared__ PieceQ q[QD];

    const int warp = threadIdx.x >> 5;
    const int lane = threadIdx.x & 31;
    const int t = threadIdx.x;

    uint32_t mbs[NSTAGE], sds[NSTAGE];
    #pragma unroll
    for (int s = 0; s < NSTAGE; s++) {
        mbs[s] = (uint32_t)__cvta_generic_to_shared(&mbar_store[s]);
        sds[s] = (uint32_t)__cvta_generic_to_shared(&sbuf[s * RPC * 64]);
    }

    if (t == 0) {
        #pragma unroll
        for (int s = 0; s < NSTAGE; s++) mbar_init(mbs[s], 1);
    }

    const float4 w0 = reinterpret_cast<const float4*>(att_w)[lane];
    const float4 w1 = reinterpret_cast<const float4*>(att_w)[lane + 32];
    const float bias = att_b[0];
    const float NEG_INF = -__int_as_float(0x7f800000);
    const float* xf = x;

    // ---- producer state (thread 0 only) ----
    int pp_start = 0, pp_end = 0, pp_c = 0, pp_n = 0;
    int pf = 0;
    int prod_seq = 0;
    bool pdone = false;

    auto fetch_piece = [&]() -> bool {
        for (;;) {
            int p = atomicAdd(&d_ticket, 1);
            if (p >= NPIECE) {
                q[pf % QD].g = -1;
                pf++;
                pdone = true;
                return false;
            }
            const int g = p >> 2, e = p & 3;
            const int b = d_bounds[g];
            const int cnt = d_bounds[g + 1] - b;
            const int st = b + (cnt * e) / PIECES_PER_G;
            const int en = b + (cnt * (e + 1)) / PIECES_PER_G;
            PieceQ pq; pq.start = st; pq.end = en; pq.g = g;
            pq.inv = 1.0f / fmaxf((float)cnt, 1.0f);
            q[pf % QD] = pq; pf++;
            if (en > st) {
                pp_start = st; pp_end = en; pp_c = 0;
                pp_n = (en - st + RPC - 1) / RPC;
                return true;
            }
        }
    };

    auto issue_one = [&]() {
        if (pdone) return;
        if (pp_c == pp_n) { if (!fetch_piece()) return; }
        const int r0 = pp_start + pp_c * RPC;
        const int rows = min(RPC, pp_end - r0);
        const int st = prod_seq & (NSTAGE - 1);
        const uint32_t bytes = (uint32_t)rows * HID * 4;
        mbar_expect_tx(mbs[st], bytes);
        bulk_g2s(sds[st], xf + (size_t)r0 * HID, bytes, mbs[st]);
        prod_seq++; pp_c++;
    };

    if (t == 0) { issue_one(); issue_one(); issue_one(); }   // prime 3 ahead
    __syncthreads();   // mbar init + queue entries visible

    // ---- consumer ----
    int cons_seq = 0;
    int cons_pidx = 0;

    for (;;) {
        const PieceQ pc = q[cons_pidx % QD];
        cons_pidx++;
        if (pc.g < 0) break;
        const int total = pc.end - pc.start;
        if (total <= 0) continue;
        const int nch = (total + RPC - 1) / RPC;

        float4 sum0 = make_float4(0.f, 0.f, 0.f, 0.f);
        float4 sum1 = make_float4(0.f, 0.f, 0.f, 0.f);
        float4 att0 = make_float4(0.f, 0.f, 0.f, 0.f);
        float4 att1 = make_float4(0.f, 0.f, 0.f, 0.f);
        float4 mx0  = make_float4(NEG_INF, NEG_INF, NEG_INF, NEG_INF);
        float4 mx1  = make_float4(NEG_INF, NEG_INF, NEG_INF, NEG_INF);

        for (int c = 0; c < nch; c++) {
            if (t == 0) issue_one();   // stream chunk cons_seq+3 (crosses pieces)

            const int st = cons_seq & (NSTAGE - 1);
            mbar_wait(mbs[st], (cons_seq >> 2) & 1);

            const int r0 = pc.start + c * RPC;
            const int rows = min(RPC, pc.end - r0);
            const int wr = 2 * warp;
            const float4* stage = &sbuf[st * RPC * 64];

            if (wr + 1 < rows) {
                const float4 a0 = stage[wr * 64 + lane];
                const float4 b0 = stage[wr * 64 + lane + 32];
                const float4 a1 = stage[(wr + 1) * 64 + lane];
                const float4 b1 = stage[(wr + 1) * 64 + lane + 32];

                float p0 = dot8(a0, b0, w0, w1);
                float p1 = dot8(a1, b1, w0, w1);
                #pragma unroll
                for (int off = 16; off > 0; off >>= 1) {
                    p0 += __shfl_xor_sync(0xffffffffu, p0, off);
                    p1 += __shfl_xor_sync(0xffffffffu, p1, off);
                }
                const float wt0 = 1.0f / (1.0f + __expf(-(p0 + bias)));
                const float wt1 = 1.0f / (1.0f + __expf(-(p1 + bias)));
                acc_node(a0, b0, wt0, sum0, sum1, mx0, mx1, att0, att1);
                acc_node(a1, b1, wt1, sum0, sum1, mx0, mx1, att0, att1);
            } else if (wr < rows) {
                const float4 a0 = stage[wr * 64 + lane];
                const float4 b0 = stage[wr * 64 + lane + 32];
                float p0 = dot8(a0, b0, w0, w1);
                #pragma unroll
                for (int off = 16; off > 0; off >>= 1)
                    p0 += __shfl_xor_sync(0xffffffffu, p0, off);
                const float wt0 = 1.0f / (1.0f + __expf(-(p0 + bias)));
                acc_node(a0, b0, wt0, sum0, sum1, mx0, mx1, att0, att1);
            }

            __syncthreads();   // stage consumed; safe for reuse at distance 3
            cons_seq++;
        }

        // ===== Epilogue: CTA-combined partials, one atomic per column =====
        float* orow = out + (size_t)pc.g * OUTW;

        // --- MEAN (scaled partial; division distributes over piece sums) ---
        reinterpret_cast<float4*>(&s_part[warp][4 * lane])[0]       = sum0;
        reinterpret_cast<float4*>(&s_part[warp][128 + 4 * lane])[0] = sum1;
        __syncthreads();
        {
            float acc = 0.f;
            #pragma unroll
            for (int w = 0; w < NWARP; w++) acc += s_part[w][t];
            atomicAdd(&orow[t], acc * pc.inv);
            if (t < HID - NTHREAD) {
                const int c = NTHREAD + t;
                float acc2 = 0.f;
                #pragma unroll
                for (int w = 0; w < NWARP; w++) acc2 += s_part[w][c];
                atomicAdd(&orow[c], acc2 * pc.inv);
            }
        }
        __syncthreads();

        // --- MAX ---
        reinterpret_cast<float4*>(&s_part[warp][4 * lane])[0]       = mx0;
        reinterpret_cast<float4*>(&s_part[warp][128 + 4 * lane])[0] = mx1;
        __syncthreads();
        {
            float acc = NEG_INF;
            #pragma unroll
            for (int w = 0; w < NWARP; w++) acc = fmaxf(acc, s_part[w][t]);
            atomicMaxFloat(&orow[HID + t], acc);
            if (t < HID - NTHREAD) {
                const int c = NTHREAD + t;
                float acc2 = NEG_INF;
                #pragma unroll
                for (int w = 0; w < NWARP; w++) acc2 = fmaxf(acc2, s_part[w][c]);
                atomicMaxFloat(&orow[HID + c], acc2);
            }
        }
        __syncthreads();

        // --- ATT ---
        reinterpret_cast<float4*>(&s_part[warp][4 * lane])[0]       = att0;
        reinterpret_cast<float4*>(&s_part[warp][128 + 4 * lane])[0] = att1;
        __syncthreads();
        {
            float acc = 0.f;
            #pragma unroll
            for (int w = 0; w < NWARP; w++) acc += s_part[w][t];
            atomicAdd(&orow[2 * HID + t], acc);
            if (t < HID - NTHREAD) {
                const int c = NTHREAD + t;
                float acc2 = 0.f;
                #pragma unroll
                for (int w = 0; w < NWARP; w++) acc2 += s_part[w][c];
                atomicAdd(&orow[2 * HID + c], acc2);
            }
        }
        __syncthreads();
    }
}

extern "C" void kernel_launch(void* const* d_in, const int* in_sizes, int n_in,
                              void* d_out, int out_size) {
    const float* x     = (const float*)d_in[0];
    const void*  batch = d_in[1];
    const float* att_w = (const float*)d_in[2];
    const float* att_b = (const float*)d_in[3];
    float*       out   = (float*)d_out;
    const int n_nodes = in_sizes[1];

    static bool attr_set = false;
    if (!attr_set) {
        cudaFuncSetAttribute(ensemble_pool_kernel,
                             cudaFuncAttributeMaxDynamicSharedMemorySize, SBUF_BYTES);
        attr_set = true;
    }

    const int setup_elems = (NOUT / 4 > n_nodes) ? NOUT / 4 : n_nodes;
    setup_kernel<<<(setup_elems + 255) / 256, 256>>>(batch, n_nodes, out);
    ensemble_pool_kernel<<<GRID, NTHREAD, SBUF_BYTES>>>(x, att_w, att_b, out);
}

// round 15
// speedup vs baseline: 1.6312x; 1.0184x over previous
#include <cuda_runtime.h>
#include <cstdint>

#define NUM_G 1024
#define HID 256
#define OUTW 768
#define NWARP 6
#define NTHREAD 192
#define RPC 12                          // rows per chunk (12KB)
#define GRID 592                        // 148 SMs x 4 CTAs
#define PIECES_PER_G 4
#define NPIECE (NUM_G * PIECES_PER_G)   // 4096
#define NOUT (NUM_G * OUTW)
#define QD 8

__device__ int d_ticket;
__device__ int d_bounds[NUM_G + 1];

struct PieceQ { int start; int end; int g; float inv; };

__device__ __forceinline__ int load_gid(const void* b, int j, int is64) {
    return is64 ? ((const int*)b)[2 * j] : ((const int*)b)[j];
}

// Fused setup: dtype probe, bounds via single read + shuffle, out init, ticket reset.
__global__ void setup_kernel(const void* __restrict__ batch_raw, int n_nodes,
                             float* __restrict__ out) {
    __shared__ int s_is64;
    if (threadIdx.x == 0) {
        const int* b32 = (const int*)batch_raw;
        int zeros = 0;
        int base = n_nodes / 2;
        for (int i = 0; i < 64; i++)
            if (b32[base + i] == 0) zeros++;
        s_is64 = (zeros > 16) ? 1 : 0;
    }
    __syncthreads();
    const int is64 = s_is64;

    const int i = blockIdx.x * blockDim.x + threadIdx.x;
    const int lane = threadIdx.x & 31;
    if (i == 0) d_ticket = 0;

    if (i < n_nodes) {
        const int cur = load_gid(batch_raw, i, is64);
        int prev = __shfl_up_sync(0xffffffffu, cur, 1);
        if (lane == 0) prev = (i == 0) ? -1 : load_gid(batch_raw, i - 1, is64);
        for (int g = prev + 1; g <= cur; g++) d_bounds[g] = i;
        if (i == n_nodes - 1)
            for (int g = cur + 1; g <= NUM_G; g++) d_bounds[g] = n_nodes;
    }

    if (i < NOUT / 4) {
        const int c = (i * 4) % OUTW;
        uint4 v = (c >= HID && c < 2 * HID)
                ? make_uint4(0xFF800000u, 0xFF800000u, 0xFF800000u, 0xFF800000u)  // -inf
                : make_uint4(0u, 0u, 0u, 0u);
        ((uint4*)out)[i] = v;
    }

#if defined(__CUDA_ARCH__) && (__CUDA_ARCH__ >= 900)
    cudaTriggerProgrammaticLaunchCompletion();
#endif
}

// Sign-aware float atomic max (correct vs -inf init and mixed signs).
__device__ __forceinline__ void atomicMaxFloat(float* addr, float v) {
    if (v >= 0.0f) atomicMax((int*)addr, __float_as_int(v));
    else           atomicMin((unsigned int*)addr, __float_as_uint(v));
}

__device__ __forceinline__ void mbar_init(uint32_t mbar, uint32_t count) {
    asm volatile("mbarrier.init.shared.b64 [%0], %1;" :: "r"(mbar), "r"(count) : "memory");
}
__device__ __forceinline__ void mbar_expect_tx(uint32_t mbar, uint32_t bytes) {
    asm volatile("mbarrier.arrive.expect_tx.shared.b64 _, [%0], %1;"
                 :: "r"(mbar), "r"(bytes) : "memory");
}
__device__ __forceinline__ void bulk_g2s(uint32_t sdst, const void* gsrc,
                                         uint32_t bytes, uint32_t mbar) {
    asm volatile("cp.async.bulk.shared::cta.global.mbarrier::complete_tx::bytes "
                 "[%0], [%1], %2, [%3];"
                 :: "r"(sdst), "l"(gsrc), "r"(bytes), "r"(mbar) : "memory");
}
__device__ __forceinline__ void mbar_wait(uint32_t mbar, uint32_t parity) {
    uint32_t done;
    asm volatile(
        "{\n\t.reg .pred p;\n\t"
        "mbarrier.try_wait.parity.acquire.cta.shared::cta.b64 p, [%1], %2;\n\t"
        "selp.b32 %0, 1, 0, p;\n\t}"
        : "=r"(done) : "r"(mbar), "r"(parity) : "memory");
    if (!done) {
        asm volatile(
            "{\n\t.reg .pred P1;\n\t"
            "WAIT_LOOP_%=:\n\t"
            "mbarrier.try_wait.parity.acquire.cta.shared::cta.b64 P1, [%0], %1, 0x989680;\n\t"
            "@P1 bra.uni WAIT_DONE_%=;\n\t"
            "bra.uni WAIT_LOOP_%=;\n\t"
            "WAIT_DONE_%=:\n\t}"
            :: "r"(mbar), "r"(parity) : "memory");
    }
}

__device__ __forceinline__ float dot8(const float4 a, const float4 b,
                                      const float4 wa, const float4 wb) {
    return a.x * wa.x + a.y * wa.y + a.z * wa.z + a.w * wa.w
         + b.x * wb.x + b.y * wb.y + b.z * wb.z + b.w * wb.w;
}

__device__ __forceinline__ void acc_node(const float4 a, const float4 b, float wt,
                                         float4& s0, float4& s1,
                                         float4& m0, float4& m1,
                                         float4& t0, float4& t1) {
    s0.x += a.x; s0.y += a.y; s0.z += a.z; s0.w += a.w;
    s1.x += b.x; s1.y += b.y; s1.z += b.z; s1.w += b.w;
    m0.x = fmaxf(m0.x, a.x); m0.y = fmaxf(m0.y, a.y);
    m0.z = fmaxf(m0.z, a.z); m0.w = fmaxf(m0.w, a.w);
    m1.x = fmaxf(m1.x, b.x); m1.y = fmaxf(m1.y, b.y);
    m1.z = fmaxf(m1.z, b.z); m1.w = fmaxf(m1.w, b.w);
    t0.x = fmaf(a.x, wt, t0.x); t0.y = fmaf(a.y, wt, t0.y);
    t0.z = fmaf(a.z, wt, t0.z); t0.w = fmaf(a.w, wt, t0.w);
    t1.x = fmaf(b.x, wt, t1.x); t1.y = fmaf(b.y, wt, t1.y);
    t1.z = fmaf(b.z, wt, t1.z); t1.w = fmaf(b.w, wt, t1.w);
}

__global__ __launch_bounds__(NTHREAD, 4)
void ensemble_pool_kernel(const float* __restrict__ x,
                          const float* __restrict__ att_w,
                          const float* __restrict__ att_b,
                          float* __restrict__ out) {
    __shared__ __align__(16) float4 sbuf[3][RPC][64];   // 36KB
    __shared__ float s_part[NWARP][HID];                // 6KB
    __shared__ __align__(8) unsigned long long mbar_store[3];
    __shared__ PieceQ q[QD];

    const int warp = threadIdx.x >> 5;
    const int lane = threadIdx.x & 31;
    const int t = threadIdx.x;

    const uint32_t mb0 = (uint32_t)__cvta_generic_to_shared(&mbar_store[0]);
    const uint32_t mb1 = (uint32_t)__cvta_generic_to_shared(&mbar_store[1]);
    const uint32_t mb2 = (uint32_t)__cvta_generic_to_shared(&mbar_store[2]);
    const uint32_t sd0 = (uint32_t)__cvta_generic_to_shared(&sbuf[0][0][0]);
    const uint32_t sd1 = (uint32_t)__cvta_generic_to_shared(&sbuf[1][0][0]);
    const uint32_t sd2 = (uint32_t)__cvta_generic_to_shared(&sbuf[2][0][0]);

    // --- setup-independent prologue (overlaps with setup kernel under PDL) ---
    if (t == 0) {
        mbar_init(mb0, 1); mbar_init(mb1, 1); mbar_init(mb2, 1);
    }
    const float4 w0 = reinterpret_cast<const float4*>(att_w)[lane];
    const float4 w1 = reinterpret_cast<const float4*>(att_w)[lane + 32];
    const float bias = att_b[0];
    const float NEG_INF = -__int_as_float(0x7f800000);
    const float* xf = x;

#if defined(__CUDA_ARCH__) && (__CUDA_ARCH__ >= 900)
    cudaGridDependencySynchronize();   // setup kernel's writes now visible
#endif

    // ---- producer state (thread 0 only) ----
    int pp_start = 0, pp_end = 0, pp_c = 0, pp_n = 0;
    int pf = 0;
    int prod_seq = 0;
    bool pdone = false;

    auto fetch_piece = [&]() -> bool {
        for (;;) {
            int p = atomicAdd(&d_ticket, 1);
            if (p >= NPIECE) {
                q[pf % QD].g = -1;
                pf++;
                pdone = true;
                return false;
            }
            const int g = p >> 2, e = p & 3;
            const int b = d_bounds[g];
            const int cnt = d_bounds[g + 1] - b;
            const int st = b + (cnt * e) / PIECES_PER_G;
            const int en = b + (cnt * (e + 1)) / PIECES_PER_G;
            PieceQ pq; pq.start = st; pq.end = en; pq.g = g;
            pq.inv = 1.0f / fmaxf((float)cnt, 1.0f);
            q[pf % QD] = pq; pf++;
            if (en > st) {
                pp_start = st; pp_end = en; pp_c = 0;
                pp_n = (en - st + RPC - 1) / RPC;
                return true;
            }
        }
    };

    auto issue_one = [&]() {
        if (pdone) return;
        if (pp_c == pp_n) { if (!fetch_piece()) return; }
        const int r0 = pp_start + pp_c * RPC;
        const int rows = min(RPC, pp_end - r0);
        const int st = prod_seq % 3;
        const uint32_t mb = (st == 0) ? mb0 : (st == 1) ? mb1 : mb2;
        const uint32_t sd = (st == 0) ? sd0 : (st == 1) ? sd1 : sd2;
        const uint32_t bytes = (uint32_t)rows * HID * 4;
        mbar_expect_tx(mb, bytes);
        bulk_g2s(sd, xf + (size_t)r0 * HID, bytes, mb);
        prod_seq++; pp_c++;
    };

    if (t == 0) { issue_one(); issue_one(); }   // prime 2 ahead
    __syncthreads();

    // ---- consumer ----
    int cons_seq = 0;
    int cons_pidx = 0;

    for (;;) {
        const PieceQ pc = q[cons_pidx % QD];
        cons_pidx++;
        if (pc.g < 0) break;
        const int total = pc.end - pc.start;
        if (total <= 0) continue;
        const int nch = (total + RPC - 1) / RPC;

        float4 sum0 = make_float4(0.f, 0.f, 0.f, 0.f);
        float4 sum1 = make_float4(0.f, 0.f, 0.f, 0.f);
        float4 att0 = make_float4(0.f, 0.f, 0.f, 0.f);
        float4 att1 = make_float4(0.f, 0.f, 0.f, 0.f);
        float4 mx0  = make_float4(NEG_INF, NEG_INF, NEG_INF, NEG_INF);
        float4 mx1  = make_float4(NEG_INF, NEG_INF, NEG_INF, NEG_INF);

        for (int c = 0; c < nch; c++) {
            if (t == 0) issue_one();   // continuous stream, crosses pieces

            const int st = cons_seq % 3;
            const uint32_t mbw = (st == 0) ? mb0 : (st == 1) ? mb1 : mb2;
            mbar_wait(mbw, (cons_seq / 3) & 1);

            const int r0 = pc.start + c * RPC;
            const int rows = min(RPC, pc.end - r0);
            const int wr = 2 * warp;

            if (wr + 1 < rows) {
                const float4 a0 = sbuf[st][wr][lane];
                const float4 b0 = sbuf[st][wr][lane + 32];
                const float4 a1 = sbuf[st][wr + 1][lane];
                const float4 b1 = sbuf[st][wr + 1][lane + 32];

                float p0 = dot8(a0, b0, w0, w1);
                float p1 = dot8(a1, b1, w0, w1);
                #pragma unroll
                for (int off = 16; off > 0; off >>= 1) {
                    p0 += __shfl_xor_sync(0xffffffffu, p0, off);
                    p1 += __shfl_xor_sync(0xffffffffu, p1, off);
                }
                const float wt0 = 1.0f / (1.0f + __expf(-(p0 + bias)));
                const float wt1 = 1.0f / (1.0f + __expf(-(p1 + bias)));
                acc_node(a0, b0, wt0, sum0, sum1, mx0, mx1, att0, att1);
                acc_node(a1, b1, wt1, sum0, sum1, mx0, mx1, att0, att1);
            } else if (wr < rows) {
                const float4 a0 = sbuf[st][wr][lane];
                const float4 b0 = sbuf[st][wr][lane + 32];
                float p0 = dot8(a0, b0, w0, w1);
                #pragma unroll
                for (int off = 16; off > 0; off >>= 1)
                    p0 += __shfl_xor_sync(0xffffffffu, p0, off);
                const float wt0 = 1.0f / (1.0f + __expf(-(p0 + bias)));
                acc_node(a0, b0, wt0, sum0, sum1, mx0, mx1, att0, att1);
            }

            __syncthreads();   // stage consumed before reuse 3 seqs later
            cons_seq++;
        }

        // ===== Epilogue: CTA-combined partials, one atomic per column =====
        float* orow = out + (size_t)pc.g * OUTW;

        // --- MEAN (scaled partial; division distributes over piece sums) ---
        reinterpret_cast<float4*>(&s_part[warp][4 * lane])[0]       = sum0;
        reinterpret_cast<float4*>(&s_part[warp][128 + 4 * lane])[0] = sum1;
        __syncthreads();
        {
            float acc = 0.f;
            #pragma unroll
            for (int w = 0; w < NWARP; w++) acc += s_part[w][t];
            atomicAdd(&orow[t], acc * pc.inv);
            if (t < HID - NTHREAD) {
                const int c = NTHREAD + t;
                float acc2 = 0.f;
                #pragma unroll
                for (int w = 0; w < NWARP; w++) acc2 += s_part[w][c];
                atomicAdd(&orow[c], acc2 * pc.inv);
            }
        }
        __syncthreads();

        // --- MAX ---
        reinterpret_cast<float4*>(&s_part[warp][4 * lane])[0]       = mx0;
        reinterpret_cast<float4*>(&s_part[warp][128 + 4 * lane])[0] = mx1;
        __syncthreads();
        {
            float acc = NEG_INF;
            #pragma unroll
            for (int w = 0; w < NWARP; w++) acc = fmaxf(acc, s_part[w][t]);
            atomicMaxFloat(&orow[HID + t], acc);
            if (t < HID - NTHREAD) {
                const int c = NTHREAD + t;
                float acc2 = NEG_INF;
                #pragma unroll
                for (int w = 0; w < NWARP; w++) acc2 = fmaxf(acc2, s_part[w][c]);
                atomicMaxFloat(&orow[HID + c], acc2);
            }
        }
        __syncthreads();

        // --- ATT ---
        reinterpret_cast<float4*>(&s_part[warp][4 * lane])[0]       = att0;
        reinterpret_cast<float4*>(&s_part[warp][128 + 4 * lane])[0] = att1;
        __syncthreads();
        {
            float acc = 0.f;
            #pragma unroll
            for (int w = 0; w < NWARP; w++) acc += s_part[w][t];
            atomicAdd(&orow[2 * HID + t], acc);
            if (t < HID - NTHREAD) {
                const int c = NTHREAD + t;
                float acc2 = 0.f;
                #pragma unroll
                for (int w = 0; w < NWARP; w++) acc2 += s_part[w][c];
                atomicAdd(&orow[2 * HID + c], acc2);
            }
        }
        __syncthreads();
    }
}

extern "C" void kernel_launch(void* const* d_in, const int* in_sizes, int n_in,
                              void* d_out, int out_size) {
    const float* x     = (const float*)d_in[0];
    const void*  batch = d_in[1];
    const float* att_w = (const float*)d_in[2];
    const float* att_b = (const float*)d_in[3];
    float*       out   = (float*)d_out;
    const int n_nodes = in_sizes[1];

    const int setup_elems = (NOUT / 4 > n_nodes) ? NOUT / 4 : n_nodes;
    setup_kernel<<<(setup_elems + 255) / 256, 256>>>(batch, n_nodes, out);

    // Main kernel with PDL: launch overlaps setup's tail; kernel gates on
    // cudaGridDependencySynchronize() before touching setup-written state.
    cudaLaunchAttribute attrs[1];
    attrs[0].id = cudaLaunchAttributeProgrammaticStreamSerialization;
    attrs[0].val.programmaticStreamSerializationAllowed = 1;
    cudaLaunchConfig_t cfg = {};
    cfg.gridDim = dim3(GRID, 1, 1);
    cfg.blockDim = dim3(NTHREAD, 1, 1);
    cfg.dynamicSmemBytes = 0;
    cfg.stream = 0;
    cfg.attrs = attrs;
    cfg.numAttrs = 1;
    cudaLaunchKernelEx(&cfg, ensemble_pool_kernel, x, att_w, att_b, out);
}